// round 2
// baseline (speedup 1.0000x reference)
#include <cuda_runtime.h>
#include <cuda_bf16.h>
#include <math_constants.h>

// Problem constants
#define NN 32768
#define KK 8192
#define DD 256
#define BETA 0.25f
#define DECAY 0.99f
#define ONE_MINUS_DECAY 0.01f
#define EPS 1e-5f
#define K_EPS 0.08192f   // fp32 nearest of 8192*1e-5 (double)

// Output layout (float32): z_q_st, commitment, idx, new_embed, new_count, new_avg
#define OFF_ZQ     0
#define OFF_COMMIT ((size_t)NN * DD)
#define OFF_IDX    (OFF_COMMIT + 1)
#define OFF_EMB    (OFF_IDX + NN)
#define OFF_CNT    (OFF_EMB + (size_t)KK * DD)
#define OFF_AVG    (OFF_CNT + KK)

// GEMM tiling
#define BM 128
#define BN 128
#define TM 8
#define TN 8

// Scratch (device globals — no allocations allowed)
__device__ float g_wnorm[KK];
__device__ float g_znorm[NN];
__device__ int   g_idx[NN];
__device__ int   g_cnt[KK];
__device__ float g_cpart[NN];
__device__ float g_nsum;

// ---------------- packed f32x2 helpers ----------------
__device__ __forceinline__ unsigned long long pack2(float x, float y) {
    unsigned long long r;
    asm("mov.b64 %0, {%1, %2};" : "=l"(r) : "f"(x), "f"(y));
    return r;
}
__device__ __forceinline__ unsigned long long fma2(unsigned long long a,
                                                   unsigned long long b,
                                                   unsigned long long c) {
    unsigned long long d;
    asm("fma.rn.f32x2 %0, %1, %2, %3;" : "=l"(d) : "l"(a), "l"(b), "l"(c));
    return d;
}
__device__ __forceinline__ void unpack2(unsigned long long v, float& lo, float& hi) {
    asm("mov.b64 {%0, %1}, %2;" : "=f"(lo), "=f"(hi) : "l"(v));
}

// ---------------- kernel 1: row norms, STRICT sequential scalar, mul+add (no fma) ----
// Replicates XLA-CPU reduce: acc = fadd(acc, fmul(v,v)) in ascending element order.
__global__ void norms_kernel(const float* __restrict__ z, const float* __restrict__ w) {
    int r = blockIdx.x * blockDim.x + threadIdx.x;
    if (r < NN) {
        const float* p = z + (size_t)r * DD;
        float s = 0.f;
        for (int i = 0; i < DD; ++i) s = __fadd_rn(s, __fmul_rn(p[i], p[i]));
        g_znorm[r] = s;
    }
    if (r < KK) {
        const float* p = w + (size_t)r * DD;
        float s = 0.f;
        for (int i = 0; i < DD; ++i) s = __fadd_rn(s, __fmul_rn(p[i], p[i]));
        g_wnorm[r] = s;
    }
}

// ---------------- kernel 2: init EMA avg region + zero counters ----------------
__global__ void init_kernel(const float* __restrict__ ema_avg,
                            float* __restrict__ out) {
    size_t i = (size_t)blockIdx.x * blockDim.x + threadIdx.x;
    if (i < (size_t)KK * DD) out[OFF_AVG + i] = __fmul_rn(DECAY, ema_avg[i]);
    if (i < KK) g_cnt[i] = 0;
}

// ---------------- kernel 3: fused GEMM + row-argmin (quantization-exact) --------
__global__ void __launch_bounds__(256, 1)
argmin_kernel(const float* __restrict__ z, const float* __restrict__ w,
              float* __restrict__ out) {
    extern __shared__ float smem[];
    float* As   = smem;                       // [DD][BM]
    float* Bs   = As + DD * BM;               // [16][BN]
    float* sval = Bs + 16 * BN;               // [BM][16]
    int*   sidx = (int*)(sval + BM * 16);     // [BM][16]

    const int tid = threadIdx.x;              // 0..255
    const int tx = tid & 15, ty = tid >> 4;
    const int rowbase = blockIdx.x * BM;

    for (int t = tid; t < BM * (DD / 4); t += 256) {
        int r  = t / (DD / 4);
        int d4 = t % (DD / 4);
        float4 v = reinterpret_cast<const float4*>(z + (size_t)(rowbase + r) * DD)[d4];
        int d = d4 * 4;
        As[(d + 0) * BM + r] = v.x;
        As[(d + 1) * BM + r] = v.y;
        As[(d + 2) * BM + r] = v.z;
        As[(d + 3) * BM + r] = v.w;
    }
    __syncthreads();

    float zn[TM];
    #pragma unroll
    for (int i = 0; i < TM; i++) zn[i] = g_znorm[rowbase + ty * TM + i];

    float best[TM];
    int   bidx[TM];
    #pragma unroll
    for (int i = 0; i < TM; i++) { best[i] = CUDART_INF_F; bidx[i] = 0x7fffffff; }

    for (int c = 0; c < KK / BN; ++c) {
        unsigned long long acc[TM][TN / 2];
        #pragma unroll
        for (int i = 0; i < TM; i++)
            #pragma unroll
            for (int j = 0; j < TN / 2; j++) acc[i][j] = 0ull;

        for (int ds = 0; ds < DD / 16; ++ds) {
            for (int t = tid; t < BN * 4; t += 256) {
                int col = t >> 2;
                int d4  = t & 3;
                float4 v = reinterpret_cast<const float4*>(
                    w + (size_t)(c * BN + col) * DD + ds * 16)[d4];
                int dd = d4 * 4;
                Bs[(dd + 0) * BN + col] = v.x;
                Bs[(dd + 1) * BN + col] = v.y;
                Bs[(dd + 2) * BN + col] = v.z;
                Bs[(dd + 3) * BN + col] = v.w;
            }
            __syncthreads();

            #pragma unroll
            for (int dd = 0; dd < 16; ++dd) {   // k strictly ascending: bit-matches
                const float* Ap = &As[(ds * 16 + dd) * BM + ty * TM];  // sequential-FMA gemm
                float4 a0 = *reinterpret_cast<const float4*>(Ap);
                float4 a1 = *reinterpret_cast<const float4*>(Ap + 4);
                unsigned long long ap[8];
                ap[0] = pack2(a0.x, a0.x); ap[1] = pack2(a0.y, a0.y);
                ap[2] = pack2(a0.z, a0.z); ap[3] = pack2(a0.w, a0.w);
                ap[4] = pack2(a1.x, a1.x); ap[5] = pack2(a1.y, a1.y);
                ap[6] = pack2(a1.z, a1.z); ap[7] = pack2(a1.w, a1.w);
                const unsigned long long* Bp =
                    reinterpret_cast<const unsigned long long*>(&Bs[dd * BN + tx * TN]);
                unsigned long long b0 = Bp[0], b1 = Bp[1], b2 = Bp[2], b3 = Bp[3];
                #pragma unroll
                for (int i = 0; i < TM; i++) {
                    acc[i][0] = fma2(ap[i], b0, acc[i][0]);
                    acc[i][1] = fma2(ap[i], b1, acc[i][1]);
                    acc[i][2] = fma2(ap[i], b2, acc[i][2]);
                    acc[i][3] = fma2(ap[i], b3, acc[i][3]);
                }
            }
            __syncthreads();
        }

        // Chunk epilogue. EXACT reference rounding:
        //   dist = fl( fl(znorm - 2*dot) + wnorm )   (2*dot is exact)
        // Strict < with ascending cols => lowest index among exact ties.
        #pragma unroll
        for (int i = 0; i < TM; i++) {
            #pragma unroll
            for (int j2 = 0; j2 < TN / 2; j2++) {
                float lo, hi;
                unpack2(acc[i][j2], lo, hi);
                int col0 = c * BN + tx * TN + j2 * 2;
                float s0 = __fadd_rn(__fsub_rn(zn[i], 2.0f * lo), g_wnorm[col0]);
                float s1 = __fadd_rn(__fsub_rn(zn[i], 2.0f * hi), g_wnorm[col0 + 1]);
                if (s0 < best[i]) { best[i] = s0; bidx[i] = col0; }
                if (s1 < best[i]) { best[i] = s1; bidx[i] = col0 + 1; }
            }
        }
    }

    #pragma unroll
    for (int i = 0; i < TM; i++) {
        sval[(ty * TM + i) * 16 + tx] = best[i];
        sidx[(ty * TM + i) * 16 + tx] = bidx[i];
    }
    __syncthreads();
    if (tid < BM) {
        float bv = sval[tid * 16];
        int   bi = sidx[tid * 16];
        #pragma unroll
        for (int t = 1; t < 16; t++) {
            float v  = sval[tid * 16 + t];
            int   ix = sidx[tid * 16 + t];
            if (v < bv || (v == bv && ix < bi)) { bv = v; bi = ix; }
        }
        g_idx[rowbase + tid] = bi;
        out[OFF_IDX + rowbase + tid] = (float)bi;
    }
}

// ---------------- kernel 4: gather z_q, commitment partials, EMA scatter --------
__global__ void gather_kernel(const float* __restrict__ z, const float* __restrict__ w,
                              float* __restrict__ out) {
    int n = blockIdx.x;
    int d = threadIdx.x;  // 256
    int k = g_idx[n];
    float ze = z[(size_t)n * DD + d];
    float wv = w[(size_t)k * DD + d];
    // z_q_st = fl(z_e + fl(z_q - z_e)) — replicate straight-through rounding
    out[OFF_ZQ + (size_t)n * DD + d] = __fadd_rn(ze, __fsub_rn(wv, ze));
    float diff = __fsub_rn(ze, wv);
    float s = __fmul_rn(diff, diff);
    __shared__ float red[8];
    #pragma unroll
    for (int o = 16; o > 0; o >>= 1) s += __shfl_down_sync(0xffffffffu, s, o);
    if ((threadIdx.x & 31) == 0) red[threadIdx.x >> 5] = s;
    __syncthreads();
    if (threadIdx.x == 0) {
        float t = 0.f;
        #pragma unroll
        for (int i = 0; i < 8; i++) t += red[i];
        g_cpart[n] = t;
        atomicAdd(&g_cnt[k], 1);
    }
    atomicAdd(&out[OFF_AVG + (size_t)k * DD + d], __fmul_rn(ONE_MINUS_DECAY, ze));
}

// ---------------- kernel 5: new_count from exact integer counts ----------------
__global__ void count_kernel(const float* __restrict__ ema_count,
                             float* __restrict__ out) {
    int k = blockIdx.x * blockDim.x + threadIdx.x;
    if (k >= KK) return;
    // new_count = fl( fl(0.99*ec) + fl(0.01*count) )  — count exact integer
    out[OFF_CNT + k] = __fadd_rn(__fmul_rn(DECAY, ema_count[k]),
                                 __fmul_rn(ONE_MINUS_DECAY, (float)g_cnt[k]));
}

// ---------------- kernel 6: deterministic reductions ----------------
__global__ void finalize_kernel(float* __restrict__ out) {
    __shared__ float sh[1024];
    int t = threadIdx.x;
    float s = 0.f;
    for (int i = t; i < NN; i += 1024) s += g_cpart[i];
    sh[t] = s;
    __syncthreads();
    for (int o = 512; o > 0; o >>= 1) {
        if (t < o) sh[t] += sh[t + o];
        __syncthreads();
    }
    if (t == 0) {
        float mean = __fdiv_rn(sh[0], (float)((size_t)NN * DD));
        out[OFF_COMMIT] = __fmul_rn(BETA, mean);
    }
    __syncthreads();
    float c = 0.f;
    for (int i = t; i < KK; i += 1024) c += out[OFF_CNT + i];
    sh[t] = c;
    __syncthreads();
    for (int o = 512; o > 0; o >>= 1) {
        if (t < o) sh[t] += sh[t + o];
        __syncthreads();
    }
    if (t == 0) g_nsum = sh[0];
}

// ---------------- kernel 7: new_embed ----------------
__global__ void embed_kernel(float* __restrict__ out) {
    size_t i = (size_t)blockIdx.x * blockDim.x + threadIdx.x;
    if (i >= (size_t)KK * DD) return;
    int k = (int)(i / DD);
    float n = g_nsum;
    float cnt = out[OFF_CNT + k];
    // cluster_size = fl( fl(fl(cnt+eps) / fl(n + K*eps)) * n )
    float cs = __fmul_rn(__fdiv_rn(__fadd_rn(cnt, EPS), __fadd_rn(n, K_EPS)), n);
    out[OFF_EMB + i] = __fdiv_rn(out[OFF_AVG + i], cs);
}

// ---------------- launch ----------------
extern "C" void kernel_launch(void* const* d_in, const int* in_sizes, int n_in,
                              void* d_out, int out_size) {
    const float* z  = (const float*)d_in[0];  // z_e      [N, D]
    const float* w  = (const float*)d_in[1];  // embedding[K, D]
    const float* ec = (const float*)d_in[2];  // ema_count[K]
    const float* ea = (const float*)d_in[3];  // ema_avg  [K, D]
    float* out = (float*)d_out;

    const int smem_bytes = (DD * BM + 16 * BN + BM * 16 + BM * 16) * 4;  // 155648
    cudaFuncSetAttribute(argmin_kernel, cudaFuncAttributeMaxDynamicSharedMemorySize,
                         smem_bytes);

    norms_kernel<<<NN / 256, 256>>>(z, w);
    init_kernel<<<(KK * DD + 255) / 256, 256>>>(ea, out);
    argmin_kernel<<<NN / BM, 256, smem_bytes>>>(z, w, out);
    gather_kernel<<<NN, 256>>>(z, w, out);
    count_kernel<<<KK / 256, 256>>>(ec, out);
    finalize_kernel<<<1, 1024>>>(out);
    embed_kernel<<<(KK * DD + 255) / 256, 256>>>(out);
    (void)in_sizes; (void)n_in; (void)out_size;
}